// round 8
// baseline (speedup 1.0000x reference)
#include <cuda_runtime.h>
#include <cuda_bf16.h>
#include <stdint.h>

// m=n=8192, k=64 fixed. Output dtype: float32 (quantized integer values).
#define COLS   8192
#define KDIM   64
#define GRIDN  148
#define THREADS 512

// smem layout (32-bit words)
#define XS_STRIDE 36                     // words per chunk (32 bf16x2 + pad) -> bank = 4c+ip
#define XS_BUF    (128*XS_STRIDE)        // 4608 words per split plane
#define XS_TOTAL  (2*3*XS_BUF)           // 27648 (2 buffers x 3 splits)
#define HS_STRIDE 72                     // words per k-pair row -> bank = 8tq+j
#define HS_PLANE  (32*HS_STRIDE)         // 2304 words per split plane
#define HS_TOTAL  (3*HS_PLANE)           // 6912
#define RED_OFF   (XS_TOTAL + HS_TOTAL)  // 34560
#define SMEM_WORDS (RED_OFF + 32)
#define SMEM_BYTES (SMEM_WORDS*4)        // 138368 B

#define MMA16(dd, A, B)                                                        \
    asm volatile("mma.sync.aligned.m16n8k16.row.col.f32.bf16.bf16.f32 "        \
        "{%0,%1,%2,%3}, {%4,%5,%6,%7}, {%8,%9}, {%0,%1,%2,%3};"                \
        : "+f"((dd)[0]), "+f"((dd)[1]), "+f"((dd)[2]), "+f"((dd)[3])           \
        : "r"((A)[0]), "r"((A)[1]), "r"((A)[2]), "r"((A)[3]),                  \
          "r"((B)[0]), "r"((B)[1]))

__device__ __forceinline__ void split3f(float v, float& f1, float& f2, float& f3) {
    f1 = __bfloat162float(__float2bfloat16(v));
    const float r1 = v - f1;
    f2 = __bfloat162float(__float2bfloat16(r1));
    f3 = __bfloat162float(__float2bfloat16(r1 - f2));
}
// pack two f32 (already bf16-rounded) into bf16x2: lo in low half
__device__ __forceinline__ uint32_t packbf(float lo, float hi) {
    return __byte_perm(__float_as_uint(lo), __float_as_uint(hi), 0x7632);
}

// ---- staging: thread t owns chunk c=t>>2, i0=(t&3)*16 of the row ----
__device__ __forceinline__ void load_raw(const float* __restrict__ src, int t, float4 raw[4]) {
    const int c = t >> 2, i0 = (t & 3) << 4;
    const float4* p = (const float4*)(src + c * 64 + i0);
    raw[0] = p[0]; raw[1] = p[1]; raw[2] = p[2]; raw[3] = p[3];
}

__device__ __forceinline__ void split_sts(uint32_t* sm, int buf, int t, const float4 raw[4]) {
    const int c = t >> 2, ip0 = (t & 3) << 3;   // word offset within chunk
    uint32_t w1[8], w2[8], w3[8];
    #pragma unroll
    for (int p = 0; p < 4; ++p) {
        float a1,a2,a3, b1,b2,b3;
        split3f(raw[p].x, a1,a2,a3); split3f(raw[p].y, b1,b2,b3);
        w1[p*2] = packbf(a1,b1); w2[p*2] = packbf(a2,b2); w3[p*2] = packbf(a3,b3);
        split3f(raw[p].z, a1,a2,a3); split3f(raw[p].w, b1,b2,b3);
        w1[p*2+1] = packbf(a1,b1); w2[p*2+1] = packbf(a2,b2); w3[p*2+1] = packbf(a3,b3);
    }
    uint32_t* base = sm + (buf*3 + 0)*XS_BUF + c*XS_STRIDE + ip0;
    *(uint4*)(base)     = make_uint4(w1[0],w1[1],w1[2],w1[3]);
    *(uint4*)(base + 4) = make_uint4(w1[4],w1[5],w1[6],w1[7]);
    base += XS_BUF;
    *(uint4*)(base)     = make_uint4(w2[0],w2[1],w2[2],w2[3]);
    *(uint4*)(base + 4) = make_uint4(w2[4],w2[5],w2[6],w2[7]);
    base += XS_BUF;
    *(uint4*)(base)     = make_uint4(w3[0],w3[1],w3[2],w3[3]);
    *(uint4*)(base + 4) = make_uint4(w3[4],w3[5],w3[6],w3[7]);
}

__global__ __launch_bounds__(THREADS, 1)
void bdq7_kernel(const float* __restrict__ x, const float* __restrict__ hmat,
                 float* __restrict__ out, int nrows)
{
    extern __shared__ uint32_t sm[];
    float* redf = (float*)(sm + RED_OFF);

    const int t  = threadIdx.x;
    const int w  = t >> 5, L = t & 31;
    const int g  = L >> 2, tq = L & 3;      // quad layout
    const int mt = w & 7, nh = w >> 3;      // warp tile: one m-tile, 4 n-tiles

    // ---- h -> 3 bf16 split planes (once per kernel) ----
    {
        const int j = t & 63;
        const int kp0 = (t >> 6) * 4;
        #pragma unroll
        for (int p = 0; p < 4; ++p) {
            const int kp = kp0 + p;
            const float ve = hmat[(2*kp)   * 64 + j];   // even k
            const float vo = hmat[(2*kp+1) * 64 + j];   // odd k
            float e1,e2,e3, o1,o2,o3;
            split3f(ve, e1,e2,e3); split3f(vo, o1,o2,o3);
            uint32_t* hb = sm + XS_TOTAL + kp*HS_STRIDE + j;
            hb[0]          = packbf(e1, o1);
            hb[HS_PLANE]   = packbf(e2, o2);
            hb[2*HS_PLANE] = packbf(e3, o3);
        }
    }

    // ---- first row -> buffer 0 ----
    long row = blockIdx.x;
    {
        float4 raw[4];
        if (row < nrows) {
            load_raw(x + row * (long)COLS, t, raw);
            split_sts(sm, 0, t, raw);
        }
    }
    __syncthreads();

    const int c0 = mt * 16 + g;             // A fragment row (chunk)
    int buf = 0;

    for (; row < nrows; row += GRIDN) {
        // ---- prefetch next row into registers (latency hidden under MMA) ----
        const long nxt = row + GRIDN;
        float4 raw[4];
        if (nxt < nrows) load_raw(x + nxt * (long)COLS, t, raw);

        // ---- MMA mainloop: 4 k-tiles x 4 n-tiles x 6 split-products ----
        float d[4][4];
        #pragma unroll
        for (int n2 = 0; n2 < 4; ++n2)
            #pragma unroll
            for (int e = 0; e < 4; ++e) d[n2][e] = 0.0f;

        const uint32_t* xsb = sm + buf * 3 * XS_BUF;

        #pragma unroll
        for (int kt = 0; kt < 4; ++kt) {
            uint32_t A[3][4];
            #pragma unroll
            for (int s = 0; s < 3; ++s) {
                const uint32_t* pa = xsb + s*XS_BUF + c0*XS_STRIDE + kt*8 + tq;
                A[s][0] = pa[0];
                A[s][1] = pa[8 * XS_STRIDE];
                A[s][2] = pa[4];
                A[s][3] = pa[8 * XS_STRIDE + 4];
            }
            #pragma unroll
            for (int nt = 0; nt < 4; ++nt) {
                const int j = (nh*4 + nt)*8 + g;
                const uint32_t* pb = sm + XS_TOTAL + (kt*8 + tq)*HS_STRIDE + j;
                uint32_t B[3][2];
                #pragma unroll
                for (int s = 0; s < 3; ++s) {
                    B[s][0] = pb[s*HS_PLANE];
                    B[s][1] = pb[s*HS_PLANE + 4*HS_STRIDE];
                }
                MMA16(d[nt], A[0], B[0]);
                MMA16(d[nt], A[0], B[1]);
                MMA16(d[nt], A[1], B[0]);
                MMA16(d[nt], A[0], B[2]);
                MMA16(d[nt], A[1], B[1]);
                MMA16(d[nt], A[2], B[0]);
            }
        }

        // ---- row absmax (warp shfl + CTA smem) ----
        float m = 0.0f;
        #pragma unroll
        for (int nt = 0; nt < 4; ++nt)
            #pragma unroll
            for (int e = 0; e < 4; ++e)
                m = fmaxf(m, fabsf(d[nt][e]));
        #pragma unroll
        for (int o = 16; o > 0; o >>= 1)
            m = fmaxf(m, __shfl_xor_sync(0xffffffffu, m, o));
        if (L == 0) redf[w] = m;
        __syncthreads();
        float a = redf[0];
        #pragma unroll
        for (int ww = 1; ww < 16; ++ww) a = fmaxf(a, redf[ww]);
        const float inv = (a == 0.0f) ? 0.0f : __fdiv_rn(127.0f, a);

        // ---- quantize (round-half-even) + store float32 ----
        float* orow = out + row * (long)COLS;
        #pragma unroll
        for (int nt = 0; nt < 4; ++nt) {
            const int j0 = (nh*4 + nt)*8 + tq*2;
            float q0 = fminf(fmaxf(rintf(d[nt][0] * inv), -128.0f), 127.0f);
            float q1 = fminf(fmaxf(rintf(d[nt][1] * inv), -128.0f), 127.0f);
            float q2 = fminf(fmaxf(rintf(d[nt][2] * inv), -128.0f), 127.0f);
            float q3 = fminf(fmaxf(rintf(d[nt][3] * inv), -128.0f), 127.0f);
            *(float2*)(orow + c0*64 + j0)       = make_float2(q0, q1);
            *(float2*)(orow + (c0+8)*64 + j0)   = make_float2(q2, q3);
        }

        // ---- stage next row into the other buffer ----
        if (nxt < nrows) split_sts(sm, buf ^ 1, t, raw);
        __syncthreads();
        buf ^= 1;
    }
}

extern "C" void kernel_launch(void* const* d_in, const int* in_sizes, int n_in,
                              void* d_out, int out_size)
{
    const float* x;
    const float* h;
    long x_elems;
    if (in_sizes[0] > in_sizes[1]) {
        x = (const float*)d_in[0]; h = (const float*)d_in[1]; x_elems = in_sizes[0];
    } else {
        x = (const float*)d_in[1]; h = (const float*)d_in[0]; x_elems = in_sizes[1];
    }
    const int nrows = (int)(x_elems / COLS);

    cudaFuncSetAttribute(bdq7_kernel, cudaFuncAttributeMaxDynamicSharedMemorySize, SMEM_BYTES);
    bdq7_kernel<<<GRIDN, THREADS, SMEM_BYTES>>>(x, h, (float*)d_out, nrows);
}